// round 14
// baseline (speedup 1.0000x reference)
#include <cuda_runtime.h>
#include <cuda_fp16.h>
#include <math.h>

// Problem constants
#define BATCH 2
#define SEQ   2048
#define DMODEL 1024
#define NHEAD 16
#define DHEAD 64
#define MROWS (BATCH * SEQ)   // 4096

// Scratch (allocation-free rule: __device__ globals)
__device__ __half g_xh [MROWS * DMODEL];         // x  fp16 [row][k]
__device__ __half g_Wqh[DMODEL * DMODEL];        // Wq^T fp16 [n][k]
__device__ __half g_Wkh[DMODEL * DMODEL];
__device__ __half g_Wvh[DMODEL * DMODEL];
__device__ __half g_Woh[DMODEL * DMODEL];
__device__ __half g_Q  [MROWS * DMODEL];         // fp16 [row][h*64+d]
__device__ __half g_K  [MROWS * DMODEL];         // fp16 [row][h*64+d]
__device__ __half g_V  [MROWS * DMODEL];         // fp16 TRANSPOSED [b][h][d][s]
__device__ __half g_AO [MROWS * DMODEL];         // fp16 [row][h*64+d]

// ---------------------------------------------------------------------------
// helpers
// ---------------------------------------------------------------------------
__device__ __forceinline__ unsigned pack_half2(float a, float b) {
    __half2 h = __floats2half2_rn(a, b);
    return *(unsigned*)&h;
}

__device__ __forceinline__ unsigned hex2(float a, float b) {
    unsigned r;
    __half2 h = __floats2half2_rn(a, b);
    asm("ex2.approx.f16x2 %0, %1;\n" : "=r"(r) : "r"(*(unsigned*)&h));
    return r;
}

__device__ __forceinline__ void mma_fp16(
    float* d, const unsigned* a, const unsigned* b, const float* c)
{
    asm volatile(
        "mma.sync.aligned.m16n8k16.row.col.f32.f16.f16.f32 "
        "{%0,%1,%2,%3}, {%4,%5,%6,%7}, {%8,%9}, {%10,%11,%12,%13};\n"
        : "=f"(d[0]), "=f"(d[1]), "=f"(d[2]), "=f"(d[3])
        : "r"(a[0]), "r"(a[1]), "r"(a[2]), "r"(a[3]),
          "r"(b[0]), "r"(b[1]),
          "f"(c[0]), "f"(c[1]), "f"(c[2]), "f"(c[3]));
}

__device__ __forceinline__ void ldsm_x4(unsigned* r, unsigned addr) {
    asm volatile(
        "ldmatrix.sync.aligned.m8n8.x4.shared.b16 {%0,%1,%2,%3}, [%4];\n"
        : "=r"(r[0]), "=r"(r[1]), "=r"(r[2]), "=r"(r[3]) : "r"(addr));
}

__device__ __forceinline__ void cp_async16(void* smem_ptr, const void* gmem_ptr) {
    unsigned saddr = (unsigned)__cvta_generic_to_shared(smem_ptr);
    asm volatile("cp.async.cg.shared.global [%0], [%1], 16;\n"
                 :: "r"(saddr), "l"(gmem_ptr));
}
__device__ __forceinline__ void cp_commit() {
    asm volatile("cp.async.commit_group;\n");
}
template<int N> __device__ __forceinline__ void cp_wait() {
    asm volatile("cp.async.wait_group %0;\n" :: "n"(N));
}

// ---------------------------------------------------------------------------
// cvt x -> fp16 (identity layout)
// ---------------------------------------------------------------------------
__global__ __launch_bounds__(256) void cvt_x_fp16(
    const float* __restrict__ x, __half* __restrict__ xh)
{
    int i = blockIdx.x * 256 + threadIdx.x;
    float4 v0 = *(const float4*)&x[(size_t)i * 8];
    float4 v1 = *(const float4*)&x[(size_t)i * 8 + 4];
    uint4 u;
    u.x = pack_half2(v0.x, v0.y);
    u.y = pack_half2(v0.z, v0.w);
    u.z = pack_half2(v1.x, v1.y);
    u.w = pack_half2(v1.z, v1.w);
    *(uint4*)&xh[(size_t)i * 8] = u;
}

// ---------------------------------------------------------------------------
// transpose + cvt weights: W[k][n] fp32 -> WT[n][k] fp16
// ---------------------------------------------------------------------------
__global__ __launch_bounds__(256) void cvt_w_t(
    const float* __restrict__ wq, const float* __restrict__ wk,
    const float* __restrict__ wv, const float* __restrict__ wo)
{
    __shared__ __half tile[32][33];
    const float* W; __half* WT;
    if (blockIdx.z == 0)      { W = wq; WT = g_Wqh; }
    else if (blockIdx.z == 1) { W = wk; WT = g_Wkh; }
    else if (blockIdx.z == 2) { W = wv; WT = g_Wvh; }
    else                      { W = wo; WT = g_Woh; }

    int tx = threadIdx.x, ty = threadIdx.y;
    int bx = blockIdx.x * 32, by = blockIdx.y * 32;
    #pragma unroll
    for (int j = 0; j < 4; j++) {
        int r = by + ty + j * 8;
        tile[ty + j * 8][tx] = __float2half(W[(size_t)r * DMODEL + bx + tx]);
    }
    __syncthreads();
    #pragma unroll
    for (int j = 0; j < 4; j++) {
        int r = bx + ty + j * 8;
        WT[(size_t)r * DMODEL + by + tx] = tile[tx][ty + j * 8];
    }
}

// ---------------------------------------------------------------------------
// fp16 GEMM, 3-stage cp.async pipeline, ldmatrix fragment loads.
// C = relu(A @ WT' + bias). BM=128 BN=128 BK=32, 256 threads, 8 warps
// 2(m)x4(n), m16n8k16. One __syncthreads per k-iter: the copy issued at
// iter 'it' targets the buffer read at 'it-1', made safe by the barrier.
// ---------------------------------------------------------------------------
#define GW 20
#define GSTG_WORDS (128 * GW)                    // per matrix per stage
#define GEMM_SMEM_WORDS (3 * 2 * GSTG_WORDS)
#define GEMM_SMEM_BYTES (GEMM_SMEM_WORDS * 4)

__global__ __launch_bounds__(256) void gemm_fp16_bias_relu(
    const __half* __restrict__ A,
    const __half* __restrict__ W0, const float* __restrict__ b0, void* __restrict__ C0,
    const __half* __restrict__ W1, const float* __restrict__ b1, void* __restrict__ C1,
    const __half* __restrict__ W2, const float* __restrict__ b2, void* __restrict__ C2,
    int modeSel)
{
    const int N = 1024, K = 1024;
    extern __shared__ unsigned smg[];
    unsigned* As = smg;                      // [3][128][20]
    unsigned* Bs = smg + 3 * GSTG_WORDS;     // [3][128][20]

    const __half* W; const float* bias; void* C;
    if (blockIdx.z == 0)      { W = W0; bias = b0; C = C0; }
    else if (blockIdx.z == 1) { W = W1; bias = b1; C = C1; }
    else                      { W = W2; bias = b2; C = C2; }
    int mode = modeSel ? ((blockIdx.z == 2) ? 2 : 1) : 0;

    int tid  = threadIdx.x;
    int lane = tid & 31;
    int warp = tid >> 5;
    int gid  = lane >> 2;
    int tig  = lane & 3;
    int l8   = lane & 7;
    int tile = lane >> 3;

    int m0w = (warp & 1) * 64;
    int n0w = (warp >> 1) * 32;

    int rowBase = blockIdx.y * 128;
    int colBase = blockIdx.x * 128;

    unsigned smem_u = (unsigned)__cvta_generic_to_shared(smg);
    unsigned as_u = smem_u;
    unsigned bs_u = smem_u + 3 * GSTG_WORDS * 4;
    unsigned aoff = (((tile & 1) * 8 + l8) * GW + (tile >> 1) * 4) * 4;
    unsigned boff = (((tile >> 1) * 8 + l8) * GW + (tile & 1) * 4) * 4;

    // loader coords
    int lr = tid >> 2;             // row 0..63 (+64 by v)
    int lc = (tid & 3) * 4;        // word col

    float acc[4][4][4] = {};

    // prologue: stages 0 and 1
    #pragma unroll
    for (int st = 0; st < 2; st++) {
        unsigned* Ad = As + st * GSTG_WORDS;
        unsigned* Bd = Bs + st * GSTG_WORDS;
        int k0 = st * 32;
        #pragma unroll
        for (int v = 0; v < 2; v++) {
            int r = lr + v * 64;
            cp_async16(&Ad[(size_t)r * GW + lc],
                       &A[(size_t)(rowBase + r) * K + k0 + lc * 2]);
            cp_async16(&Bd[(size_t)r * GW + lc],
                       &W[(size_t)(colBase + r) * K + k0 + lc * 2]);
        }
        cp_commit();
    }

    int buf = 0;
    #pragma unroll 1
    for (int it = 0; it < 32; it++) {
        if (it < 31) cp_wait<1>(); else cp_wait<0>();
        __syncthreads();

        // issue stage it+2 into buffer (it+2)%3 == buffer read at it-1
        if (it + 2 < 32) {
            int st = it + 2;
            int sb = st - (st / 3) * 3;
            unsigned* Ad = As + sb * GSTG_WORDS;
            unsigned* Bd = Bs + sb * GSTG_WORDS;
            int k0 = st * 32;
            #pragma unroll
            for (int v = 0; v < 2; v++) {
                int r = lr + v * 64;
                cp_async16(&Ad[(size_t)r * GW + lc],
                           &A[(size_t)(rowBase + r) * K + k0 + lc * 2]);
                cp_async16(&Bd[(size_t)r * GW + lc],
                           &W[(size_t)(colBase + r) * K + k0 + lc * 2]);
            }
            cp_commit();
        }

        unsigned ab_u = as_u + buf * GSTG_WORDS * 4;
        unsigned bb_u = bs_u + buf * GSTG_WORDS * 4;

        #pragma unroll
        for (int ks = 0; ks < 2; ks++) {
            unsigned af[4][4], bf[2][4];
            #pragma unroll
            for (int mt = 0; mt < 4; mt++)
                ldsm_x4(af[mt], ab_u + (((m0w + mt * 16) * GW + ks * 8) * 4) + aoff);
            ldsm_x4(bf[0], bb_u + (((n0w     ) * GW + ks * 8) * 4) + boff);
            ldsm_x4(bf[1], bb_u + (((n0w + 16) * GW + ks * 8) * 4) + boff);
            #pragma unroll
            for (int mt = 0; mt < 4; mt++) {
                mma_fp16(acc[mt][0], af[mt], &bf[0][0], acc[mt][0]);
                mma_fp16(acc[mt][1], af[mt], &bf[0][2], acc[mt][1]);
                mma_fp16(acc[mt][2], af[mt], &bf[1][0], acc[mt][2]);
                mma_fp16(acc[mt][3], af[mt], &bf[1][2], acc[mt][3]);
            }
        }
        buf = (buf == 2) ? 0 : buf + 1;
    }

    // epilogue
    #pragma unroll
    for (int mt = 0; mt < 4; mt++) {
        #pragma unroll
        for (int nt = 0; nt < 4; nt++) {
            int col = colBase + n0w + nt * 8 + tig * 2;
            float bv0 = bias[col], bv1 = bias[col + 1];
            int r0 = rowBase + m0w + mt * 16 + gid;
            float v00 = fmaxf(acc[mt][nt][0] + bv0, 0.f);
            float v01 = fmaxf(acc[mt][nt][1] + bv1, 0.f);
            float v10 = fmaxf(acc[mt][nt][2] + bv0, 0.f);
            float v11 = fmaxf(acc[mt][nt][3] + bv1, 0.f);
            if (mode == 0) {
                float* Cf = (float*)C;
                float2 o0, o1;
                o0.x = v00; o0.y = v01;
                o1.x = v10; o1.y = v11;
                *(float2*)&Cf[(size_t)r0 * N + col]       = o0;
                *(float2*)&Cf[(size_t)(r0 + 8) * N + col] = o1;
            } else if (mode == 1) {
                unsigned* Cw = (unsigned*)C;
                Cw[((size_t)r0 * N + col) >> 1]       = pack_half2(v00, v01);
                Cw[((size_t)(r0 + 8) * N + col) >> 1] = pack_half2(v10, v11);
            } else {
                __half* VT = (__half*)C;
                int b = r0 >> 11, s = r0 & 2047;
                int h = col >> 6, d = col & 63;
                size_t base = ((size_t)(b * NHEAD + h) * DHEAD + d) * SEQ + s;
                VT[base]            = __float2half(v00);
                VT[base + SEQ]      = __float2half(v01);
                VT[base + 8]        = __float2half(v10);
                VT[base + SEQ + 8]  = __float2half(v11);
            }
        }
    }
}

// ---------------------------------------------------------------------------
// fp16 flash attention v5: v4 math (no-max softmax, register P, ones-column
// l, ex2.approx, two 32-key halves) with a 3-stage cp.async ring: one
// __syncthreads per chunk; the copy issued at chunk kc targets the stage
// read at kc-1 (safe after the barrier); cp_wait<1> keeps a full chunk of
// prefetch distance.
// ---------------------------------------------------------------------------
#define ATW 36
#define AT_STG_WORDS (64 * ATW)                  // per matrix per stage
#define AT_K_WORDS  (3 * AT_STG_WORDS)
#define AT_V_WORDS  (3 * AT_STG_WORDS)
#define AT_SMEM_BYTES ((AT_K_WORDS + AT_V_WORDS + 3 * 64) * 4)

__global__ __launch_bounds__(128, 3) void attention_mma(
    const __half* __restrict__ Q, const __half* __restrict__ K,
    const __half* __restrict__ VT, const int* __restrict__ mask,
    __half* __restrict__ O)
{
    extern __shared__ unsigned sm[];
    unsigned* Ks  = sm;                        // [3][64][36]
    unsigned* Vs  = Ks + AT_K_WORDS;           // [3][64][36]
    int*      mk  = (int*)(Vs + AT_V_WORDS);   // [3][64]

    int tid  = threadIdx.x;
    int lane = tid & 31;
    int warp = tid >> 5;
    int gid  = lane >> 2;
    int tig  = lane & 3;
    int l8   = lane & 7;
    int tile = lane >> 3;
    int qt = blockIdx.x;
    int h  = blockIdx.y;
    int b  = blockIdx.z;
    int qbase = qt * 128;
    int m0 = warp * 32;
    const float SCL2E = 0.125f * 1.4426950408889634f;   // scale * log2(e)

    const size_t headOff = (size_t)h * DHEAD;
    const size_t bRow = (size_t)b * SEQ;
    const __half* VTh = VT + (size_t)(b * NHEAD + h) * DHEAD * SEQ;

    unsigned smem_u = (unsigned)__cvta_generic_to_shared(sm);
    unsigned ks_u = smem_u;
    unsigned vs_u = smem_u + AT_K_WORDS * 4;
    unsigned boff = (((tile >> 1) * 8 + l8) * ATW + (tile & 1) * 4) * 4;

    // constant all-ones B fragment (column n=0)
    unsigned bones = (gid == 0) ? 0x3C003C00u : 0u;
    unsigned bf_ones[2] = {bones, bones};

    // --- Q fragments ---
    unsigned qf[2][4][4];
    {
        const unsigned* Qw = (const unsigned*)(Q + (bRow + qbase + m0) * DMODEL + headOff);
        #pragma unroll
        for (int mt = 0; mt < 2; mt++) {
            #pragma unroll
            for (int kt = 0; kt < 4; kt++) {
                size_t r0 = (size_t)(mt * 16 + gid) * 512;
                size_t r1 = (size_t)(mt * 16 + gid + 8) * 512;
                qf[mt][kt][0] = Qw[r0 + kt * 8 + tig];
                qf[mt][kt][1] = Qw[r1 + kt * 8 + tig];
                qf[mt][kt][2] = Qw[r0 + kt * 8 + tig + 4];
                qf[mt][kt][3] = Qw[r1 + kt * 8 + tig + 4];
            }
        }
    }

    // --- prologue: issue chunks 0 and 1 ---
    #pragma unroll
    for (int st = 0; st < 2; st++) {
        unsigned* Kd = Ks + st * AT_STG_WORDS;
        unsigned* Vd = Vs + st * AT_STG_WORDS;
        #pragma unroll
        for (int v = 0; v < 4; v++) {
            int idx = tid + v * 128;
            int row = idx >> 3, cw = (idx & 7) * 4;
            cp_async16(&Kd[(size_t)row * ATW + cw],
                       &K[(bRow + st * 64 + row) * DMODEL + headOff + cw * 2]);
            cp_async16(&Vd[(size_t)row * ATW + cw],
                       &VTh[(size_t)row * SEQ + st * 64 + cw * 2]);
        }
        if (tid < 16) cp_async16(&mk[st * 64 + tid * 4],
                                 &mask[bRow + st * 64 + tid * 4]);
        cp_commit();
    }

    float oacc[2][8][4] = {};
    float lacc[2][4] = {};

    int buf = 0;
    #pragma unroll 1
    for (int kc = 0; kc < SEQ / 64; kc++) {
        if (kc < SEQ / 64 - 1) cp_wait<1>(); else cp_wait<0>();
        __syncthreads();

        // issue chunk kc+2 into stage (kc+2)%3 (read at kc-1; safe now)
        if (kc + 2 < SEQ / 64) {
            int st = kc + 2;
            int sb = st - (st / 3) * 3;
            unsigned* Kd = Ks + sb * AT_STG_WORDS;
            unsigned* Vd = Vs + sb * AT_STG_WORDS;
            #pragma unroll
            for (int v = 0; v < 4; v++) {
                int idx = tid + v * 128;
                int row = idx >> 3, cw = (idx & 7) * 4;
                cp_async16(&Kd[(size_t)row * ATW + cw],
                           &K[(bRow + st * 64 + row) * DMODEL + headOff + cw * 2]);
                cp_async16(&Vd[(size_t)row * ATW + cw],
                           &VTh[(size_t)row * SEQ + st * 64 + cw * 2]);
            }
            if (tid < 16) cp_async16(&mk[sb * 64 + tid * 4],
                                     &mask[bRow + st * 64 + tid * 4]);
            cp_commit();
        }

        unsigned kb_u = ks_u + buf * AT_STG_WORDS * 4;
        unsigned vb_u = vs_u + buf * AT_STG_WORDS * 4;
        int* mkb = mk + buf * 64;

        // mask bits for this chunk
        unsigned mlo = __ballot_sync(0xffffffffu, mkb[lane] != 0);
        unsigned mhi = __ballot_sync(0xffffffffu, mkb[lane + 32] != 0);

        // --- two 32-key halves: S -> P -> PV ---
        #pragma unroll
        for (int half = 0; half < 2; half++) {
            float s[2][4][4] = {};
            #pragma unroll
            for (int kt = 0; kt < 4; kt++) {
                #pragma unroll
                for (int j = 0; j < 2; j++) {
                    int jj = half * 2 + j;
                    unsigned bq[4];
                    ldsm_x4(bq, kb_u + ((jj * 16 * ATW + kt * 8) * 4) + boff);
                    mma_fp16(s[0][2*j],     qf[0][kt], &bq[0], s[0][2*j]);
                    mma_fp16(s[1][2*j],     qf[1][kt], &bq[0], s[1][2*j]);
                    mma_fp16(s[0][2*j + 1], qf[0][kt], &bq[2], s[0][2*j + 1]);
                    mma_fp16(s[1][2*j + 1], qf[1][kt], &bq[2], s[1][2*j + 1]);
                }
            }

            unsigned pfh[2][4][2];
            unsigned mw = half ? mhi : mlo;
            #pragma unroll
            for (int nt = 0; nt < 4; nt++) {
                int c0 = (nt * 8 + 2 * tig) & 31;
                bool k0m = (mw >> c0) & 1;
                bool k1m = (mw >> (c0 + 1)) & 1;
                #pragma unroll
                for (int mt = 0; mt < 2; mt++) {
                    float t0 = k0m ? 0.f : s[mt][nt][0] * SCL2E;
                    float t1 = k1m ? 0.f : s[mt][nt][1] * SCL2E;
                    float t2 = k0m ? 0.f : s[mt][nt][2] * SCL2E;
                    float t3 = k1m ? 0.f : s[mt][nt][3] * SCL2E;
                    pfh[mt][nt][0] = hex2(t0, t1);
                    pfh[mt][nt][1] = hex2(t2, t3);
                }
            }

            #pragma unroll
            for (int kl = 0; kl < 2; kl++) {
                int kk = half * 2 + kl;
                unsigned af0[4] = { pfh[0][2*kl][0], pfh[0][2*kl][1],
                                    pfh[0][2*kl+1][0], pfh[0][2*kl+1][1] };
                unsigned af1[4] = { pfh[1][2*kl][0], pfh[1][2*kl][1],
                                    pfh[1][2*kl+1][0], pfh[1][2*kl+1][1] };
                #pragma unroll
                for (int j = 0; j < 4; j++) {
                    unsigned bv[4];
                    ldsm_x4(bv, vb_u + ((j * 16 * ATW + kk * 8) * 4) + boff);
                    mma_fp16(oacc[0][2*j],     af0, &bv[0], oacc[0][2*j]);
                    mma_fp16(oacc[1][2*j],     af1, &bv[0], oacc[1][2*j]);
                    mma_fp16(oacc[0][2*j + 1], af0, &bv[2], oacc[0][2*j + 1]);
                    mma_fp16(oacc[1][2*j + 1], af1, &bv[2], oacc[1][2*j + 1]);
                }
                mma_fp16(lacc[0], af0, bf_ones, lacc[0]);
                mma_fp16(lacc[1], af1, bf_ones, lacc[1]);
            }
        }
        buf = (buf == 2) ? 0 : buf + 1;
    }

    // --- epilogue: fetch l (col 0 on tig==0 lanes), normalize, store ---
    unsigned* Ow = (unsigned*)O;
    #pragma unroll
    for (int mt = 0; mt < 2; mt++) {
        float l0 = __shfl_sync(0xffffffffu, lacc[mt][0], lane & 0x1c);
        float l1 = __shfl_sync(0xffffffffu, lacc[mt][2], lane & 0x1c);
        float inv0 = 1.f / l0;
        float inv1 = 1.f / l1;
        size_t r0 = ((bRow + qbase + m0 + mt * 16 + gid) * DMODEL + headOff) >> 1;
        size_t r1 = ((bRow + qbase + m0 + mt * 16 + gid + 8) * DMODEL + headOff) >> 1;
        #pragma unroll
        for (int dt = 0; dt < 8; dt++) {
            int cw = dt * 4 + tig;
            Ow[r0 + cw] = pack_half2(oacc[mt][dt][0] * inv0, oacc[mt][dt][1] * inv0);
            Ow[r1 + cw] = pack_half2(oacc[mt][dt][2] * inv1, oacc[mt][dt][3] * inv1);
        }
    }
}

// ---------------------------------------------------------------------------
// launch
// ---------------------------------------------------------------------------
extern "C" void kernel_launch(void* const* d_in, const int* in_sizes, int n_in,
                              void* d_out, int out_size)
{
    const float* x    = (const float*)d_in[0];
    const int*   mask = (const int*)  d_in[1];
    const float* Wq   = (const float*)d_in[2];
    const float* bq   = (const float*)d_in[3];
    const float* Wk   = (const float*)d_in[4];
    const float* bk   = (const float*)d_in[5];
    const float* Wv   = (const float*)d_in[6];
    const float* bv   = (const float*)d_in[7];
    const float* Wo   = (const float*)d_in[8];
    const float* bo   = (const float*)d_in[9];
    float* out = (float*)d_out;

    __half *xh, *Wqh, *Wkh, *Wvh, *Woh, *Qp, *Kp, *Vp, *AOp;
    cudaGetSymbolAddress((void**)&xh,  g_xh);
    cudaGetSymbolAddress((void**)&Wqh, g_Wqh);
    cudaGetSymbolAddress((void**)&Wkh, g_Wkh);
    cudaGetSymbolAddress((void**)&Wvh, g_Wvh);
    cudaGetSymbolAddress((void**)&Woh, g_Woh);
    cudaGetSymbolAddress((void**)&Qp,  g_Q);
    cudaGetSymbolAddress((void**)&Kp,  g_K);
    cudaGetSymbolAddress((void**)&Vp,  g_V);
    cudaGetSymbolAddress((void**)&AOp, g_AO);

    cudaFuncSetAttribute(gemm_fp16_bias_relu,
                         cudaFuncAttributeMaxDynamicSharedMemorySize, GEMM_SMEM_BYTES);
    cudaFuncSetAttribute(attention_mma,
                         cudaFuncAttributeMaxDynamicSharedMemorySize, AT_SMEM_BYTES);

    // convert inputs
    cvt_x_fp16<<<MROWS * DMODEL / 8 / 256, 256>>>(x, xh);
    cvt_w_t<<<dim3(32, 32, 4), dim3(32, 8)>>>(Wq, Wk, Wv, Wo);

    // fused Q/K/V projections (Q,K natural fp16; V transposed fp16)
    dim3 gqkv(1024 / 128, 4096 / 128, 3);
    gemm_fp16_bias_relu<<<gqkv, 256, GEMM_SMEM_BYTES>>>(xh,
                                       Wqh, bq, Qp,
                                       Wkh, bk, Kp,
                                       Wvh, bv, Vp, 1);

    attention_mma<<<dim3(SEQ / 128, NHEAD, BATCH), 128, AT_SMEM_BYTES>>>(
        Qp, Kp, Vp, mask, AOp);

    // output projection (fp32 store)
    dim3 go(1024 / 128, 4096 / 128, 1);
    gemm_fp16_bias_relu<<<go, 256, GEMM_SMEM_BYTES>>>(AOp,
                                     Woh, bo, out,
                                     Woh, bo, out,
                                     Woh, bo, out, 0);
}

// round 16
// speedup vs baseline: 1.1012x; 1.1012x over previous
#include <cuda_runtime.h>
#include <cuda_fp16.h>
#include <math.h>

// Problem constants
#define BATCH 2
#define SEQ   2048
#define DMODEL 1024
#define NHEAD 16
#define DHEAD 64
#define MROWS (BATCH * SEQ)   // 4096

// Scratch (allocation-free rule: __device__ globals)
__device__ __half g_xh [MROWS * DMODEL];         // x  fp16 [row][k]
__device__ __half g_Wqh[DMODEL * DMODEL];        // Wq^T fp16 [n][k]
__device__ __half g_Wkh[DMODEL * DMODEL];
__device__ __half g_Wvh[DMODEL * DMODEL];
__device__ __half g_Woh[DMODEL * DMODEL];
__device__ __half g_Q  [MROWS * DMODEL];         // fp16 [row][h*64+d]
__device__ __half g_K  [MROWS * DMODEL];         // fp16 [row][h*64+d]
__device__ __half g_V  [MROWS * DMODEL];         // fp16 TRANSPOSED [b][h][d][s]
__device__ __half g_AO [MROWS * DMODEL];         // fp16 [row][h*64+d]

// ---------------------------------------------------------------------------
// helpers
// ---------------------------------------------------------------------------
__device__ __forceinline__ unsigned pack_half2(float a, float b) {
    __half2 h = __floats2half2_rn(a, b);
    return *(unsigned*)&h;
}

__device__ __forceinline__ unsigned hex2(float a, float b) {
    unsigned r;
    __half2 h = __floats2half2_rn(a, b);
    asm("ex2.approx.f16x2 %0, %1;\n" : "=r"(r) : "r"(*(unsigned*)&h));
    return r;
}

__device__ __forceinline__ void mma_fp16(
    float* d, const unsigned* a, const unsigned* b, const float* c)
{
    asm volatile(
        "mma.sync.aligned.m16n8k16.row.col.f32.f16.f16.f32 "
        "{%0,%1,%2,%3}, {%4,%5,%6,%7}, {%8,%9}, {%10,%11,%12,%13};\n"
        : "=f"(d[0]), "=f"(d[1]), "=f"(d[2]), "=f"(d[3])
        : "r"(a[0]), "r"(a[1]), "r"(a[2]), "r"(a[3]),
          "r"(b[0]), "r"(b[1]),
          "f"(c[0]), "f"(c[1]), "f"(c[2]), "f"(c[3]));
}

__device__ __forceinline__ void ldsm_x4(unsigned* r, unsigned addr) {
    asm volatile(
        "ldmatrix.sync.aligned.m8n8.x4.shared.b16 {%0,%1,%2,%3}, [%4];\n"
        : "=r"(r[0]), "=r"(r[1]), "=r"(r[2]), "=r"(r[3]) : "r"(addr));
}

__device__ __forceinline__ void cp_async16(void* smem_ptr, const void* gmem_ptr) {
    unsigned saddr = (unsigned)__cvta_generic_to_shared(smem_ptr);
    asm volatile("cp.async.cg.shared.global [%0], [%1], 16;\n"
                 :: "r"(saddr), "l"(gmem_ptr));
}
__device__ __forceinline__ void cp_commit() {
    asm volatile("cp.async.commit_group;\n");
}
template<int N> __device__ __forceinline__ void cp_wait() {
    asm volatile("cp.async.wait_group %0;\n" :: "n"(N));
}

// ---------------------------------------------------------------------------
// cvt x -> fp16 (identity layout)
// ---------------------------------------------------------------------------
__global__ __launch_bounds__(256) void cvt_x_fp16(
    const float* __restrict__ x, __half* __restrict__ xh)
{
    int i = blockIdx.x * 256 + threadIdx.x;
    float4 v0 = *(const float4*)&x[(size_t)i * 8];
    float4 v1 = *(const float4*)&x[(size_t)i * 8 + 4];
    uint4 u;
    u.x = pack_half2(v0.x, v0.y);
    u.y = pack_half2(v0.z, v0.w);
    u.z = pack_half2(v1.x, v1.y);
    u.w = pack_half2(v1.z, v1.w);
    *(uint4*)&xh[(size_t)i * 8] = u;
}

// ---------------------------------------------------------------------------
// transpose + cvt weights: W[k][n] fp32 -> WT[n][k] fp16
// ---------------------------------------------------------------------------
__global__ __launch_bounds__(256) void cvt_w_t(
    const float* __restrict__ wq, const float* __restrict__ wk,
    const float* __restrict__ wv, const float* __restrict__ wo)
{
    __shared__ __half tile[32][33];
    const float* W; __half* WT;
    if (blockIdx.z == 0)      { W = wq; WT = g_Wqh; }
    else if (blockIdx.z == 1) { W = wk; WT = g_Wkh; }
    else if (blockIdx.z == 2) { W = wv; WT = g_Wvh; }
    else                      { W = wo; WT = g_Woh; }

    int tx = threadIdx.x, ty = threadIdx.y;
    int bx = blockIdx.x * 32, by = blockIdx.y * 32;
    #pragma unroll
    for (int j = 0; j < 4; j++) {
        int r = by + ty + j * 8;
        tile[ty + j * 8][tx] = __float2half(W[(size_t)r * DMODEL + bx + tx]);
    }
    __syncthreads();
    #pragma unroll
    for (int j = 0; j < 4; j++) {
        int r = bx + ty + j * 8;
        WT[(size_t)r * DMODEL + by + tx] = tile[tx][ty + j * 8];
    }
}

// ---------------------------------------------------------------------------
// fp16 GEMM, BK=64, double-buffered cp.async, ldmatrix fragment loads.
// C = relu(A @ WT' + bias). BM=128 BN=128 BK=64, 256 threads, 8 warps
// 2(m)x4(n), m16n8k16. 16 k-iterations (halved barrier/wait count vs BK=32).
// SMEM word stride 36 (=4 mod 32, frag LDS conflict-free).
// ---------------------------------------------------------------------------
#define GW2 36
#define GSTG (128 * GW2)                       // words per matrix per stage
#define GEMM_SMEM_WORDS (2 * 2 * GSTG)
#define GEMM_SMEM_BYTES (GEMM_SMEM_WORDS * 4)

__global__ __launch_bounds__(256) void gemm_fp16_bias_relu(
    const __half* __restrict__ A,
    const __half* __restrict__ W0, const float* __restrict__ b0, void* __restrict__ C0,
    const __half* __restrict__ W1, const float* __restrict__ b1, void* __restrict__ C1,
    const __half* __restrict__ W2, const float* __restrict__ b2, void* __restrict__ C2,
    int modeSel)
{
    const int N = 1024, K = 1024;
    extern __shared__ unsigned smg[];
    unsigned* As = smg;                  // [2][128][36]
    unsigned* Bs = smg + 2 * GSTG;       // [2][128][36]

    const __half* W; const float* bias; void* C;
    if (blockIdx.z == 0)      { W = W0; bias = b0; C = C0; }
    else if (blockIdx.z == 1) { W = W1; bias = b1; C = C1; }
    else                      { W = W2; bias = b2; C = C2; }
    int mode = modeSel ? ((blockIdx.z == 2) ? 2 : 1) : 0;

    int tid  = threadIdx.x;
    int lane = tid & 31;
    int warp = tid >> 5;
    int gid  = lane >> 2;
    int tig  = lane & 3;
    int l8   = lane & 7;
    int tile = lane >> 3;

    int m0w = (warp & 1) * 64;
    int n0w = (warp >> 1) * 32;

    int rowBase = blockIdx.y * 128;
    int colBase = blockIdx.x * 128;

    unsigned smem_u = (unsigned)__cvta_generic_to_shared(smg);
    unsigned as_u = smem_u;
    unsigned bs_u = smem_u + 2 * GSTG * 4;
    unsigned aoff = (((tile & 1) * 8 + l8) * GW2 + (tile >> 1) * 4) * 4;
    unsigned boff = (((tile >> 1) * 8 + l8) * GW2 + (tile & 1) * 4) * 4;

    float acc[4][4][4] = {};

    // loader: per matrix per stage = 128 rows x 8 chunks = 1024 cp16;
    // 4 per thread: idx = tid + v*256, row = idx>>3, cw = (idx&7)*4
    {
        #pragma unroll
        for (int v = 0; v < 4; v++) {
            int idx = tid + v * 256;
            int r = idx >> 3, cw = (idx & 7) * 4;
            cp_async16(&As[(size_t)r * GW2 + cw], &A[(size_t)(rowBase + r) * K + cw * 2]);
            cp_async16(&Bs[(size_t)r * GW2 + cw], &W[(size_t)(colBase + r) * K + cw * 2]);
        }
        cp_commit();
    }

    #pragma unroll 1
    for (int it = 0; it < 16; it++) {
        int buf = it & 1;
        if (it + 1 < 16) {
            int k0n = (it + 1) * 64;
            unsigned* An = As + (buf ^ 1) * GSTG;
            unsigned* Bn = Bs + (buf ^ 1) * GSTG;
            #pragma unroll
            for (int v = 0; v < 4; v++) {
                int idx = tid + v * 256;
                int r = idx >> 3, cw = (idx & 7) * 4;
                cp_async16(&An[(size_t)r * GW2 + cw],
                           &A[(size_t)(rowBase + r) * K + k0n + cw * 2]);
                cp_async16(&Bn[(size_t)r * GW2 + cw],
                           &W[(size_t)(colBase + r) * K + k0n + cw * 2]);
            }
            cp_commit();
            cp_wait<1>();
        } else {
            cp_wait<0>();
        }
        __syncthreads();

        unsigned ab_u = as_u + buf * GSTG * 4;
        unsigned bb_u = bs_u + buf * GSTG * 4;

        #pragma unroll
        for (int ks = 0; ks < 4; ks++) {
            unsigned af[4][4], bf[2][4];
            #pragma unroll
            for (int mt = 0; mt < 4; mt++)
                ldsm_x4(af[mt], ab_u + (((m0w + mt * 16) * GW2 + ks * 8) * 4) + aoff);
            ldsm_x4(bf[0], bb_u + (((n0w     ) * GW2 + ks * 8) * 4) + boff);
            ldsm_x4(bf[1], bb_u + (((n0w + 16) * GW2 + ks * 8) * 4) + boff);
            #pragma unroll
            for (int mt = 0; mt < 4; mt++) {
                mma_fp16(acc[mt][0], af[mt], &bf[0][0], acc[mt][0]);
                mma_fp16(acc[mt][1], af[mt], &bf[0][2], acc[mt][1]);
                mma_fp16(acc[mt][2], af[mt], &bf[1][0], acc[mt][2]);
                mma_fp16(acc[mt][3], af[mt], &bf[1][2], acc[mt][3]);
            }
        }
        __syncthreads();
    }

    // epilogue
    #pragma unroll
    for (int mt = 0; mt < 4; mt++) {
        #pragma unroll
        for (int nt = 0; nt < 4; nt++) {
            int col = colBase + n0w + nt * 8 + tig * 2;
            float bv0 = bias[col], bv1 = bias[col + 1];
            int r0 = rowBase + m0w + mt * 16 + gid;
            float v00 = fmaxf(acc[mt][nt][0] + bv0, 0.f);
            float v01 = fmaxf(acc[mt][nt][1] + bv1, 0.f);
            float v10 = fmaxf(acc[mt][nt][2] + bv0, 0.f);
            float v11 = fmaxf(acc[mt][nt][3] + bv1, 0.f);
            if (mode == 0) {
                float* Cf = (float*)C;
                float2 o0, o1;
                o0.x = v00; o0.y = v01;
                o1.x = v10; o1.y = v11;
                *(float2*)&Cf[(size_t)r0 * N + col]       = o0;
                *(float2*)&Cf[(size_t)(r0 + 8) * N + col] = o1;
            } else if (mode == 1) {
                unsigned* Cw = (unsigned*)C;
                Cw[((size_t)r0 * N + col) >> 1]       = pack_half2(v00, v01);
                Cw[((size_t)(r0 + 8) * N + col) >> 1] = pack_half2(v10, v11);
            } else {
                // V^T scatter: [b][h][d][s]
                __half* VT = (__half*)C;
                int b = r0 >> 11, s = r0 & 2047;
                int h = col >> 6, d = col & 63;
                size_t base = ((size_t)(b * NHEAD + h) * DHEAD + d) * SEQ + s;
                VT[base]            = __float2half(v00);
                VT[base + SEQ]      = __float2half(v01);
                VT[base + 8]        = __float2half(v10);
                VT[base + SEQ + 8]  = __float2half(v11);
            }
        }
    }
}

// ---------------------------------------------------------------------------
// fp16 flash attention v5 (R14, best measured): no-max softmax, register P,
// ones-column l, ex2.approx, two 32-key halves, 3-stage cp.async ring.
// ---------------------------------------------------------------------------
#define ATW 36
#define AT_STG_WORDS (64 * ATW)
#define AT_K_WORDS  (3 * AT_STG_WORDS)
#define AT_V_WORDS  (3 * AT_STG_WORDS)
#define AT_SMEM_BYTES ((AT_K_WORDS + AT_V_WORDS + 3 * 64) * 4)

__global__ __launch_bounds__(128, 3) void attention_mma(
    const __half* __restrict__ Q, const __half* __restrict__ K,
    const __half* __restrict__ VT, const int* __restrict__ mask,
    __half* __restrict__ O)
{
    extern __shared__ unsigned sm[];
    unsigned* Ks  = sm;                        // [3][64][36]
    unsigned* Vs  = Ks + AT_K_WORDS;           // [3][64][36]
    int*      mk  = (int*)(Vs + AT_V_WORDS);   // [3][64]

    int tid  = threadIdx.x;
    int lane = tid & 31;
    int warp = tid >> 5;
    int gid  = lane >> 2;
    int tig  = lane & 3;
    int l8   = lane & 7;
    int tile = lane >> 3;
    int qt = blockIdx.x;
    int h  = blockIdx.y;
    int b  = blockIdx.z;
    int qbase = qt * 128;
    int m0 = warp * 32;
    const float SCL2E = 0.125f * 1.4426950408889634f;

    const size_t headOff = (size_t)h * DHEAD;
    const size_t bRow = (size_t)b * SEQ;
    const __half* VTh = VT + (size_t)(b * NHEAD + h) * DHEAD * SEQ;

    unsigned smem_u = (unsigned)__cvta_generic_to_shared(sm);
    unsigned ks_u = smem_u;
    unsigned vs_u = smem_u + AT_K_WORDS * 4;
    unsigned boff = (((tile >> 1) * 8 + l8) * ATW + (tile & 1) * 4) * 4;

    unsigned bones = (gid == 0) ? 0x3C003C00u : 0u;
    unsigned bf_ones[2] = {bones, bones};

    unsigned qf[2][4][4];
    {
        const unsigned* Qw = (const unsigned*)(Q + (bRow + qbase + m0) * DMODEL + headOff);
        #pragma unroll
        for (int mt = 0; mt < 2; mt++) {
            #pragma unroll
            for (int kt = 0; kt < 4; kt++) {
                size_t r0 = (size_t)(mt * 16 + gid) * 512;
                size_t r1 = (size_t)(mt * 16 + gid + 8) * 512;
                qf[mt][kt][0] = Qw[r0 + kt * 8 + tig];
                qf[mt][kt][1] = Qw[r1 + kt * 8 + tig];
                qf[mt][kt][2] = Qw[r0 + kt * 8 + tig + 4];
                qf[mt][kt][3] = Qw[r1 + kt * 8 + tig + 4];
            }
        }
    }

    #pragma unroll
    for (int st = 0; st < 2; st++) {
        unsigned* Kd = Ks + st * AT_STG_WORDS;
        unsigned* Vd = Vs + st * AT_STG_WORDS;
        #pragma unroll
        for (int v = 0; v < 4; v++) {
            int idx = tid + v * 128;
            int row = idx >> 3, cw = (idx & 7) * 4;
            cp_async16(&Kd[(size_t)row * ATW + cw],
                       &K[(bRow + st * 64 + row) * DMODEL + headOff + cw * 2]);
            cp_async16(&Vd[(size_t)row * ATW + cw],
                       &VTh[(size_t)row * SEQ + st * 64 + cw * 2]);
        }
        if (tid < 16) cp_async16(&mk[st * 64 + tid * 4],
                                 &mask[bRow + st * 64 + tid * 4]);
        cp_commit();
    }

    float oacc[2][8][4] = {};
    float lacc[2][4] = {};

    int buf = 0;
    #pragma unroll 1
    for (int kc = 0; kc < SEQ / 64; kc++) {
        if (kc < SEQ / 64 - 1) cp_wait<1>(); else cp_wait<0>();
        __syncthreads();

        if (kc + 2 < SEQ / 64) {
            int st = kc + 2;
            int sb = st - (st / 3) * 3;
            unsigned* Kd = Ks + sb * AT_STG_WORDS;
            unsigned* Vd = Vs + sb * AT_STG_WORDS;
            #pragma unroll
            for (int v = 0; v < 4; v++) {
                int idx = tid + v * 128;
                int row = idx >> 3, cw = (idx & 7) * 4;
                cp_async16(&Kd[(size_t)row * ATW + cw],
                           &K[(bRow + st * 64 + row) * DMODEL + headOff + cw * 2]);
                cp_async16(&Vd[(size_t)row * ATW + cw],
                           &VTh[(size_t)row * SEQ + st * 64 + cw * 2]);
            }
            if (tid < 16) cp_async16(&mk[sb * 64 + tid * 4],
                                     &mask[bRow + st * 64 + tid * 4]);
            cp_commit();
        }

        unsigned kb_u = ks_u + buf * AT_STG_WORDS * 4;
        unsigned vb_u = vs_u + buf * AT_STG_WORDS * 4;
        int* mkb = mk + buf * 64;

        unsigned mlo = __ballot_sync(0xffffffffu, mkb[lane] != 0);
        unsigned mhi = __ballot_sync(0xffffffffu, mkb[lane + 32] != 0);

        #pragma unroll
        for (int half = 0; half < 2; half++) {
            float s[2][4][4] = {};
            #pragma unroll
            for (int kt = 0; kt < 4; kt++) {
                #pragma unroll
                for (int j = 0; j < 2; j++) {
                    int jj = half * 2 + j;
                    unsigned bq[4];
                    ldsm_x4(bq, kb_u + ((jj * 16 * ATW + kt * 8) * 4) + boff);
                    mma_fp16(s[0][2*j],     qf[0][kt], &bq[0], s[0][2*j]);
                    mma_fp16(s[1][2*j],     qf[1][kt], &bq[0], s[1][2*j]);
                    mma_fp16(s[0][2*j + 1], qf[0][kt], &bq[2], s[0][2*j + 1]);
                    mma_fp16(s[1][2*j + 1], qf[1][kt], &bq[2], s[1][2*j + 1]);
                }
            }

            unsigned pfh[2][4][2];
            unsigned mw = half ? mhi : mlo;
            #pragma unroll
            for (int nt = 0; nt < 4; nt++) {
                int c0 = (nt * 8 + 2 * tig) & 31;
                bool k0m = (mw >> c0) & 1;
                bool k1m = (mw >> (c0 + 1)) & 1;
                #pragma unroll
                for (int mt = 0; mt < 2; mt++) {
                    float t0 = k0m ? 0.f : s[mt][nt][0] * SCL2E;
                    float t1 = k1m ? 0.f : s[mt][nt][1] * SCL2E;
                    float t2 = k0m ? 0.f : s[mt][nt][2] * SCL2E;
                    float t3 = k1m ? 0.f : s[mt][nt][3] * SCL2E;
                    pfh[mt][nt][0] = hex2(t0, t1);
                    pfh[mt][nt][1] = hex2(t2, t3);
                }
            }

            #pragma unroll
            for (int kl = 0; kl < 2; kl++) {
                int kk = half * 2 + kl;
                unsigned af0[4] = { pfh[0][2*kl][0], pfh[0][2*kl][1],
                                    pfh[0][2*kl+1][0], pfh[0][2*kl+1][1] };
                unsigned af1[4] = { pfh[1][2*kl][0], pfh[1][2*kl][1],
                                    pfh[1][2*kl+1][0], pfh[1][2*kl+1][1] };
                #pragma unroll
                for (int j = 0; j < 4; j++) {
                    unsigned bv[4];
                    ldsm_x4(bv, vb_u + ((j * 16 * ATW + kk * 8) * 4) + boff);
                    mma_fp16(oacc[0][2*j],     af0, &bv[0], oacc[0][2*j]);
                    mma_fp16(oacc[1][2*j],     af1, &bv[0], oacc[1][2*j]);
                    mma_fp16(oacc[0][2*j + 1], af0, &bv[2], oacc[0][2*j + 1]);
                    mma_fp16(oacc[1][2*j + 1], af1, &bv[2], oacc[1][2*j + 1]);
                }
                mma_fp16(lacc[0], af0, bf_ones, lacc[0]);
                mma_fp16(lacc[1], af1, bf_ones, lacc[1]);
            }
        }
        buf = (buf == 2) ? 0 : buf + 1;
    }

    unsigned* Ow = (unsigned*)O;
    #pragma unroll
    for (int mt = 0; mt < 2; mt++) {
        float l0 = __shfl_sync(0xffffffffu, lacc[mt][0], lane & 0x1c);
        float l1 = __shfl_sync(0xffffffffu, lacc[mt][2], lane & 0x1c);
        float inv0 = 1.f / l0;
        float inv1 = 1.f / l1;
        size_t r0 = ((bRow + qbase + m0 + mt * 16 + gid) * DMODEL + headOff) >> 1;
        size_t r1 = ((bRow + qbase + m0 + mt * 16 + gid + 8) * DMODEL + headOff) >> 1;
        #pragma unroll
        for (int dt = 0; dt < 8; dt++) {
            int cw = dt * 4 + tig;
            Ow[r0 + cw] = pack_half2(oacc[mt][dt][0] * inv0, oacc[mt][dt][1] * inv0);
            Ow[r1 + cw] = pack_half2(oacc[mt][dt][2] * inv1, oacc[mt][dt][3] * inv1);
        }
    }
}

// ---------------------------------------------------------------------------
// launch
// ---------------------------------------------------------------------------
extern "C" void kernel_launch(void* const* d_in, const int* in_sizes, int n_in,
                              void* d_out, int out_size)
{
    const float* x    = (const float*)d_in[0];
    const int*   mask = (const int*)  d_in[1];
    const float* Wq   = (const float*)d_in[2];
    const float* bq   = (const float*)d_in[3];
    const float* Wk   = (const float*)d_in[4];
    const float* bk   = (const float*)d_in[5];
    const float* Wv   = (const float*)d_in[6];
    const float* bv   = (const float*)d_in[7];
    const float* Wo   = (const float*)d_in[8];
    const float* bo   = (const float*)d_in[9];
    float* out = (float*)d_out;

    __half *xh, *Wqh, *Wkh, *Wvh, *Woh, *Qp, *Kp, *Vp, *AOp;
    cudaGetSymbolAddress((void**)&xh,  g_xh);
    cudaGetSymbolAddress((void**)&Wqh, g_Wqh);
    cudaGetSymbolAddress((void**)&Wkh, g_Wkh);
    cudaGetSymbolAddress((void**)&Wvh, g_Wvh);
    cudaGetSymbolAddress((void**)&Woh, g_Woh);
    cudaGetSymbolAddress((void**)&Qp,  g_Q);
    cudaGetSymbolAddress((void**)&Kp,  g_K);
    cudaGetSymbolAddress((void**)&Vp,  g_V);
    cudaGetSymbolAddress((void**)&AOp, g_AO);

    cudaFuncSetAttribute(gemm_fp16_bias_relu,
                         cudaFuncAttributeMaxDynamicSharedMemorySize, GEMM_SMEM_BYTES);
    cudaFuncSetAttribute(attention_mma,
                         cudaFuncAttributeMaxDynamicSharedMemorySize, AT_SMEM_BYTES);

    // convert inputs
    cvt_x_fp16<<<MROWS * DMODEL / 8 / 256, 256>>>(x, xh);
    cvt_w_t<<<dim3(32, 32, 4), dim3(32, 8)>>>(Wq, Wk, Wv, Wo);

    // fused Q/K/V projections (Q,K natural fp16; V transposed fp16)
    dim3 gqkv(1024 / 128, 4096 / 128, 3);
    gemm_fp16_bias_relu<<<gqkv, 256, GEMM_SMEM_BYTES>>>(xh,
                                       Wqh, bq, Qp,
                                       Wkh, bk, Kp,
                                       Wvh, bv, Vp, 1);

    attention_mma<<<dim3(SEQ / 128, NHEAD, BATCH), 128, AT_SMEM_BYTES>>>(
        Qp, Kp, Vp, mask, AOp);

    // output projection (fp32 store)
    dim3 go(1024 / 128, 4096 / 128, 1);
    gemm_fp16_bias_relu<<<go, 256, GEMM_SMEM_BYTES>>>(AOp,
                                     Woh, bo, out,
                                     Woh, bo, out,
                                     Woh, bo, out, 0);
}